// round 2
// baseline (speedup 1.0000x reference)
#include <cuda_runtime.h>

// ---------------------------------------------------------------------------
// ConvLSTM: B=16, T=16, C=1, H=W=64, HID=64, two layers of 3x3 conv LSTM cells
// then a 1x1 conv head with ReLU.
//
// Strategy (round 0, fp32 direct conv, compute-bound):
//  - fused conv+gate+LSTM-update kernel per (layer, timestep)
//  - block = 256 threads, 32x32 spatial tile, 2x2 px/thread,
//    4 hidden channels (16 gate channels) per block -> 64 accumulators/thread
//  - SMEM staging of 34x34 input halo tile + 144 gate weights per in-channel
//  - h state ping-pong (cross-block RAW hazard), c updated in place
// ---------------------------------------------------------------------------

#define HSZ (16 * 64 * 64 * 64)   // one state buffer: [B=16, HID=64, 64, 64]

__device__ float g_h0[2][HSZ];
__device__ float g_c0[HSZ];
__device__ float g_h1[2][HSZ];
__device__ float g_c1[HSZ];

__device__ __forceinline__ float fsig(float x) {
    return 1.0f / (1.0f + __expf(-x));
}
__device__ __forceinline__ float ftanh(float x) {
    // tanh(x) = 2*sigmoid(2x) - 1 ; robust at |x| large (exp -> 0 or inf)
    return 2.0f / (1.0f + __expf(-2.0f * x)) - 1.0f;
}

__global__ void zero_state_kernel() {
    int i = blockIdx.x * blockDim.x + threadIdx.x;
    if (i < HSZ) {
        g_h0[0][i] = 0.f;
        g_c0[i]    = 0.f;
        g_h1[0][i] = 0.f;
        g_c1[i]    = 0.f;
    }
}

// One ConvLSTM cell step.
//  A    : first CHA input channels (x_t for layer0, h0_new for layer1),
//         channel stride 4096, batch stride aBatchStride.
//  Hin  : previous hidden state (64 channels, [B,64,64,64]).
//  W    : [256, CHA+64, 3, 3] gate weights, bias: [256].
//  C    : cell state, updated in place. Hout: new hidden state (ping-pong).
// Grid: (4 spatial tiles of 32x32, 16 hid-blocks of 4 channels, 16 batch)
template <int CHA>
__global__ void __launch_bounds__(256)
convlstm_step(const float* __restrict__ A, int aBatchStride,
              const float* __restrict__ Hin,
              const float* __restrict__ W,
              const float* __restrict__ bias,
              float* __restrict__ C,
              float* __restrict__ Hout)
{
    constexpr int CIN = CHA + 64;
    __shared__ float s_in[34 * 34];
    __shared__ float s_w[144];        // 16 gate channels x 9 taps

    const int tid = threadIdx.x;
    const int b   = blockIdx.z;
    const int hb  = blockIdx.y;                 // hid base = hb*4
    const int tY0 = (blockIdx.x >> 1) * 32;
    const int tX0 = (blockIdx.x & 1) * 32;
    const int ty2 = (tid >> 4) * 2;             // 0..30, thread's pixel row base in tile
    const int tx2 = (tid & 15) * 2;

    float acc[64];
#pragma unroll
    for (int i = 0; i < 64; i++) acc[i] = 0.f;

    const float* Abase = A + (size_t)b * aBatchStride;
    const float* Hbase = Hin + ((size_t)b * 64) * 4096;

    for (int ic = 0; ic < CIN; ic++) {
        const float* plane = (ic < CHA) ? (Abase + ic * 4096)
                                        : (Hbase + (ic - CHA) * 4096);
        __syncthreads();
        // stage 34x34 halo tile (zero-padded SAME boundary)
#pragma unroll
        for (int i = tid; i < 34 * 34; i += 256) {
            int r  = i / 34, cc = i - r * 34;
            int gy = tY0 + r - 1, gx = tX0 + cc - 1;
            float v = 0.f;
            if ((unsigned)gy < 64u && (unsigned)gx < 64u) v = plane[gy * 64 + gx];
            s_in[i] = v;
        }
        // stage this block's 16 gate-channel weight rows for input channel ic
        if (tid < 144) {
            int gc = tid / 9, k = tid - gc * 9;
            int oc = (gc >> 2) * 64 + hb * 4 + (gc & 3);   // gate g = gc>>2, hid j = gc&3
            s_w[tid] = W[((size_t)oc * CIN + ic) * 9 + k];
        }
        __syncthreads();

        // 4x4 register input patch for the 2x2 pixel micro-tile
        float rin[16];
#pragma unroll
        for (int r = 0; r < 4; r++)
#pragma unroll
            for (int c = 0; c < 4; c++)
                rin[r * 4 + c] = s_in[(ty2 + r) * 34 + (tx2 + c)];

#pragma unroll
        for (int gc = 0; gc < 16; gc++) {
            float w[9];
#pragma unroll
            for (int k = 0; k < 9; k++) w[k] = s_w[gc * 9 + k];
#pragma unroll
            for (int pr = 0; pr < 2; pr++)
#pragma unroll
                for (int pc = 0; pc < 2; pc++) {
                    float s = acc[gc * 4 + pr * 2 + pc];
#pragma unroll
                    for (int ky = 0; ky < 3; ky++)
#pragma unroll
                        for (int kx = 0; kx < 3; kx++)
                            s = fmaf(w[ky * 3 + kx], rin[(pr + ky) * 4 + (pc + kx)], s);
                    acc[gc * 4 + pr * 2 + pc] = s;
                }
        }
    }

    // LSTM elementwise update: gates order in channel dim = [i, f, o, g] * 64
#pragma unroll
    for (int j = 0; j < 4; j++) {
        const int hid = hb * 4 + j;
        const float bi = bias[hid];
        const float bf = bias[64 + hid];
        const float bo = bias[128 + hid];
        const float bg = bias[192 + hid];
#pragma unroll
        for (int pr = 0; pr < 2; pr++)
#pragma unroll
            for (int pc = 0; pc < 2; pc++) {
                const int p  = pr * 2 + pc;
                const int gy = tY0 + ty2 + pr;
                const int gx = tX0 + tx2 + pc;
                const size_t idx = (((size_t)b * 64 + hid) << 12) + gy * 64 + gx;
                const float iv = fsig(acc[j * 4 + p] + bi);
                const float fv = fsig(acc[(4 + j) * 4 + p] + bf);
                const float ov = fsig(acc[(8 + j) * 4 + p] + bo);
                const float gv = ftanh(acc[(12 + j) * 4 + p] + bg);
                const float cn = fv * C[idx] + iv * gv;
                C[idx]    = cn;
                Hout[idx] = ov * ftanh(cn);
            }
    }
}

// 1x1 conv head (64 -> 1) + ReLU over h1 final state.
__global__ void head_kernel(const float* __restrict__ h1,
                            const float* __restrict__ wh,
                            const float* __restrict__ bh,
                            float* __restrict__ out)
{
    int idx = blockIdx.x * blockDim.x + threadIdx.x;  // 65536 = 16 * 4096
    int b   = idx >> 12;
    int pix = idx & 4095;
    const float* base = h1 + (((size_t)b * 64) << 12) + pix;
    float s = bh[0];
#pragma unroll
    for (int c = 0; c < 64; c++)
        s = fmaf(wh[c], base[(size_t)c << 12], s);
    out[idx] = fmaxf(s, 0.f);
}

extern "C" void kernel_launch(void* const* d_in, const int* in_sizes, int n_in,
                              void* d_out, int out_size)
{
    const float* x  = (const float*)d_in[0];   // [16,16,1,64,64]
    const float* w0 = (const float*)d_in[1];   // [256,65,3,3]
    const float* b0 = (const float*)d_in[2];   // [256]
    const float* w1 = (const float*)d_in[3];   // [256,128,3,3]
    const float* b1 = (const float*)d_in[4];   // [256]
    const float* wh = (const float*)d_in[5];   // [1,64,1,1]
    const float* bh = (const float*)d_in[6];   // [1]
    float* out = (float*)d_out;                // [16,1,64,64]

    float *h0, *c0, *h1, *c1;
    cudaGetSymbolAddress((void**)&h0, g_h0);
    cudaGetSymbolAddress((void**)&c0, g_c0);
    cudaGetSymbolAddress((void**)&h1, g_h1);
    cudaGetSymbolAddress((void**)&c1, g_c1);

    zero_state_kernel<<<HSZ / 256, 256>>>();

    dim3 grid(4, 16, 16);
    for (int t = 0; t < 16; t++) {
        float* h0r = h0 + (size_t)(t & 1) * HSZ;
        float* h0w = h0 + (size_t)((t + 1) & 1) * HSZ;
        float* h1r = h1 + (size_t)(t & 1) * HSZ;
        float* h1w = h1 + (size_t)((t + 1) & 1) * HSZ;
        // layer 0: input = [x_t (1ch) ; h0_prev (64ch)]
        convlstm_step<1><<<grid, 256>>>(x + (size_t)t * 4096, 16 * 4096,
                                        h0r, w0, b0, c0, h0w);
        // layer 1: input = [h0_new (64ch) ; h1_prev (64ch)]
        convlstm_step<64><<<grid, 256>>>(h0w, 64 * 4096,
                                         h1r, w1, b1, c1, h1w);
    }
    // after t=15, new h1 lives in buffer ((15+1)&1) = 0
    head_kernel<<<65536 / 256, 256>>>(h1, wh, bh, out);
}